// round 14
// baseline (speedup 1.0000x reference)
#include <cuda_runtime.h>
#include <cuda_fp16.h>
#include <cstdint>

#define MAXN 100000
#define MAXE 3200000
#define FDIM 128   // IN == OUT == 128

// Scratch (device globals: allocation-free per harness rules)
__device__ __half   g_h[(size_t)MAXN * FDIM];    // (x@W) fp16, then dis .* it (25.6 MB)
__device__ uint32_t g_Wfrag[16384];              // W tf32 fragment layout (64 KB)
__device__ float    g_dis[MAXN];                 // rsqrt(deg + 1)
__device__ int      g_deg[MAXN];                 // zero at steady state (gather restores)
__device__ int      g_start[MAXN];               // CSR bin start
__device__ int      g_pos[MAXE];                 // within-bin position per edge (12.8 MB)
__device__ int      g_csr[MAXE];                 // packed bins (12.8 MB)
__device__ int      g_cursor;                    // zero at steady state (gather restores)
__device__ int      g_is32;

// ---------------------------------------------------------------------------
// 0) dtype probe (idempotent)
__global__ void k_probe(const void* __restrict__ ei, int n) {
    const long long* p = (const long long*)ei;
    int is32 = 0;
    for (int k = 0; k < 64; k++) {
        long long v = p[k];
        if (v < 0 || v >= (long long)n) { is32 = 1; break; }
    }
    g_is32 = is32;
}

__device__ __forceinline__ int load_idx(const void* p, long long idx, int is32) {
    if (is32) return ((const int*)p)[idx];
    return (int)((const long long*)p)[idx];
}

// 1) histogram over dst + record within-bin position per edge
__global__ void k_deg(const void* __restrict__ ei, int e, int n) {
    int i = blockIdx.x * blockDim.x + threadIdx.x;
    int base = i * 4;
    if (base >= e) return;
    int is32 = g_is32;
    if (is32 && ((e & 3) == 0) && base + 4 <= e) {
        int4 d4 = ((const int4*)((const int*)ei + e))[i];
        int p0 = ((unsigned)d4.x < (unsigned)n) ? atomicAdd(&g_deg[d4.x], 1) : 0;
        int p1 = ((unsigned)d4.y < (unsigned)n) ? atomicAdd(&g_deg[d4.y], 1) : 0;
        int p2 = ((unsigned)d4.z < (unsigned)n) ? atomicAdd(&g_deg[d4.z], 1) : 0;
        int p3 = ((unsigned)d4.w < (unsigned)n) ? atomicAdd(&g_deg[d4.w], 1) : 0;
        ((int4*)g_pos)[i] = make_int4(p0, p1, p2, p3);   // coalesced
    } else {
        int hi = base + 4 < e ? base + 4 : e;
        for (int k = base; k < hi; k++) {
            int d = load_idx(ei, (long long)e + k, is32);
            g_pos[k] = ((unsigned)d < (unsigned)n) ? atomicAdd(&g_deg[d], 1) : 0;
        }
    }
}

// 2) reserve bins + dis = rsqrt(deg+1). g_deg is kept (gather needs it, then zeroes it)
__global__ void k_reserve(int n) {
    int i = blockIdx.x * blockDim.x + threadIdx.x;
    if (i < n) {
        int d = g_deg[i];
        g_start[i] = atomicAdd(&g_cursor, d);
        g_dis[i]   = rsqrtf((float)(d + 1));
    }
}

// 3) fill CSR — atomic-free: position precomputed by k_deg
__global__ void k_fill(const void* __restrict__ ei, int e, int n) {
    int i = blockIdx.x * blockDim.x + threadIdx.x;
    int base = i * 4;
    if (base >= e) return;
    int is32 = g_is32;
    if (is32 && ((e & 3) == 0) && base + 4 <= e) {
        int4 s4 = ((const int4*)((const int*)ei))[i];
        int4 d4 = ((const int4*)((const int*)ei + e))[i];
        int4 p4 = ((const int4*)g_pos)[i];
        if ((unsigned)d4.x < (unsigned)n && (unsigned)s4.x < (unsigned)n)
            g_csr[g_start[d4.x] + p4.x] = s4.x;
        if ((unsigned)d4.y < (unsigned)n && (unsigned)s4.y < (unsigned)n)
            g_csr[g_start[d4.y] + p4.y] = s4.y;
        if ((unsigned)d4.z < (unsigned)n && (unsigned)s4.z < (unsigned)n)
            g_csr[g_start[d4.z] + p4.z] = s4.z;
        if ((unsigned)d4.w < (unsigned)n && (unsigned)s4.w < (unsigned)n)
            g_csr[g_start[d4.w] + p4.w] = s4.w;
    } else {
        int hi = base + 4 < e ? base + 4 : e;
        for (int k = base; k < hi; k++) {
            int s = load_idx(ei, k, is32);
            int d = load_idx(ei, (long long)e + k, is32);
            if ((unsigned)d < (unsigned)n && (unsigned)s < (unsigned)n)
                g_csr[g_start[d] + g_pos[k]] = s;
        }
    }
}

// ---------------------------------------------------------------------------
// 4a) pre-swizzle W into tf32 m16n8k8 B-fragment layout (global, 64 KB)
__global__ void k_wprep(const float* __restrict__ W) {
    int i = blockIdx.x * blockDim.x + threadIdx.x;   // 8192 entries
    if (i >= 8192) return;
    int lane = i & 31;
    int nt   = (i >> 5) & 15;
    int ks   = i >> 9;
    int k    = ks * 8 + (lane & 3);
    int c    = nt * 8 + (lane >> 2);
    uint32_t t0, t1;
    asm("cvt.rna.tf32.f32 %0, %1;" : "=r"(t0) : "f"(W[(size_t)k * FDIM + c]));
    asm("cvt.rna.tf32.f32 %0, %1;" : "=r"(t1) : "f"(W[(size_t)(k + 4) * FDIM + c]));
    *(uint2*)&g_Wfrag[(size_t)i * 2] = make_uint2(t0, t1);
}

// 4b) GEMM: g_h = fp16(x @ W)  (raw; dis applied by k_scale in place)
__global__ void __launch_bounds__(256, 2)
k_gemm_tf32(const float* __restrict__ x, int n) {
    extern __shared__ uint32_t sm[];
    uint32_t* A = sm;            // [16 ks][8 w][32 lane][4 reg] = 64 KB

    const int row0 = blockIdx.x * 128;
    const int tid  = threadIdx.x;

    for (int i = tid; i < 16 * 8 * 32; i += 256) {
        int lane = i & 31;
        int w    = (i >> 5) & 7;
        int ks   = i >> 8;
        int r    = row0 + w * 16 + (lane >> 2);
        int c    = ks * 8 + (lane & 3);
        float v0 = 0.f, v1 = 0.f, v2 = 0.f, v3 = 0.f;
        if (r < n)     { v0 = x[(size_t)r * FDIM + c];       v2 = x[(size_t)r * FDIM + c + 4]; }
        if (r + 8 < n) { v1 = x[(size_t)(r + 8) * FDIM + c]; v3 = x[(size_t)(r + 8) * FDIM + c + 4]; }
        uint32_t t0, t1, t2, t3;
        asm("cvt.rna.tf32.f32 %0, %1;" : "=r"(t0) : "f"(v0));
        asm("cvt.rna.tf32.f32 %0, %1;" : "=r"(t1) : "f"(v1));
        asm("cvt.rna.tf32.f32 %0, %1;" : "=r"(t2) : "f"(v2));
        asm("cvt.rna.tf32.f32 %0, %1;" : "=r"(t3) : "f"(v3));
        *(uint4*)&A[(size_t)i * 4] = make_uint4(t0, t1, t2, t3);
    }
    __syncthreads();

    const int lane = tid & 31;
    const int w    = tid >> 5;

    float acc[16][4];
#pragma unroll
    for (int nt = 0; nt < 16; nt++) { acc[nt][0] = acc[nt][1] = acc[nt][2] = acc[nt][3] = 0.f; }

    const uint2* __restrict__ Bf = (const uint2*)g_Wfrag;

#pragma unroll
    for (int ks = 0; ks < 16; ks++) {
        uint4 a = *(const uint4*)&A[(((ks * 8 + w) * 32 + lane)) * 4];
#pragma unroll
        for (int nt = 0; nt < 16; nt++) {
            uint2 b = __ldg(&Bf[(ks * 16 + nt) * 32 + lane]);
            asm volatile(
                "mma.sync.aligned.m16n8k8.row.col.f32.tf32.tf32.f32 "
                "{%0,%1,%2,%3}, {%4,%5,%6,%7}, {%8,%9}, {%0,%1,%2,%3};"
                : "+f"(acc[nt][0]), "+f"(acc[nt][1]), "+f"(acc[nt][2]), "+f"(acc[nt][3])
                : "r"(a.x), "r"(a.y), "r"(a.z), "r"(a.w), "r"(b.x), "r"(b.y));
        }
    }

    // epilogue: fp16 raw (c0,c1 adjacent cols -> one half2)
    int r0 = row0 + w * 16 + (lane >> 2);
    int cp = lane & 3;                       // half2 index within an 8-col group
    if (r0 < n) {
        __half2* p = (__half2*)(g_h + (size_t)r0 * FDIM) + cp;
#pragma unroll
        for (int nt = 0; nt < 16; nt++)
            p[nt * 4] = __floats2half2_rn(acc[nt][0], acc[nt][1]);
    }
    if (r0 + 8 < n) {
        __half2* p = (__half2*)(g_h + (size_t)(r0 + 8) * FDIM) + cp;
#pragma unroll
        for (int nt = 0; nt < 16; nt++)
            p[nt * 4] = __floats2half2_rn(acc[nt][2], acc[nt][3]);
    }
}

// 4c) scale in place: g_h *= dis[row]  (fp16 read/write, fp32 math)
__global__ void k_scale(int n) {
    int i = blockIdx.x * blockDim.x + threadIdx.x;   // n*16 threads, 8 halves each
    if (i >= n * 16) return;
    int node = i >> 4;
    float d = g_dis[node];
    uint4 raw = ((const uint4*)g_h)[i];
    uint32_t r[4] = {raw.x, raw.y, raw.z, raw.w};
#pragma unroll
    for (int t = 0; t < 4; t++) {
        float2 f = __half22float2(*reinterpret_cast<const __half2*>(&r[t]));
        __half2 h = __floats2half2_rn(d * f.x, d * f.y);
        r[t] = *reinterpret_cast<const uint32_t*>(&h);
    }
    ((uint4*)g_h)[i] = make_uint4(r[0], r[1], r[2], r[3]);
}

// ---------------------------------------------------------------------------
// 5) gather: one warp per node; 8 row-loads in flight per lane (measured-best).
//    deg from g_deg (then zeroed for next replay); node 0 restores g_cursor.
__global__ void k_gather(const float* __restrict__ b, float* __restrict__ out, int n) {
    int node = (blockIdx.x * blockDim.x + threadIdx.x) >> 5;
    int lane = threadIdx.x & 31;
    if (node >= n) return;
    if (node == 0 && lane == 0) g_cursor = 0;   // self-restore

    const uint2* __restrict__ h2 = (const uint2*)g_h;

    float di  = g_dis[node];
    int   s0  = g_start[node];
    int   deg = g_deg[node];
    if (lane == 0) g_deg[node] = 0;             // self-restore for next replay

    uint2 raw = h2[(size_t)node * 32 + lane];
    float2 f0 = __half22float2(*reinterpret_cast<const __half2*>(&raw.x));
    float2 f1 = __half22float2(*reinterpret_cast<const __half2*>(&raw.y));
    float4 acc = make_float4(f0.x, f0.y, f1.x, f1.y);

    int nfull = deg & ~31;

    // full chunks: 32 coalesced indices, 4 batches of 8 in-flight loads
    for (int base = 0; base < nfull; base += 32) {
        int s = g_csr[s0 + base + lane];
#pragma unroll
        for (int jj = 0; jj < 32; jj += 8) {
            int sj[8];
#pragma unroll
            for (int t = 0; t < 8; t++) sj[t] = __shfl_sync(0xffffffffu, s, jj + t);
            uint2 v[8];
#pragma unroll
            for (int t = 0; t < 8; t++) v[t] = h2[(size_t)sj[t] * 32 + lane];
#pragma unroll
            for (int t = 0; t < 8; t++) {
                float2 a0 = __half22float2(*reinterpret_cast<const __half2*>(&v[t].x));
                float2 a1 = __half22float2(*reinterpret_cast<const __half2*>(&v[t].y));
                acc.x += a0.x; acc.y += a0.y; acc.z += a1.x; acc.w += a1.y;
            }
        }
    }

    // tail: 8-wide batches, then scalar
    int rem = deg - nfull;
    if (rem > 0) {
        int s = (lane < rem) ? g_csr[s0 + nfull + lane] : 0;
        int j = 0;
        for (; j + 8 <= rem; j += 8) {
            int sj[8];
#pragma unroll
            for (int t = 0; t < 8; t++) sj[t] = __shfl_sync(0xffffffffu, s, j + t);
            uint2 v[8];
#pragma unroll
            for (int t = 0; t < 8; t++) v[t] = h2[(size_t)sj[t] * 32 + lane];
#pragma unroll
            for (int t = 0; t < 8; t++) {
                float2 a0 = __half22float2(*reinterpret_cast<const __half2*>(&v[t].x));
                float2 a1 = __half22float2(*reinterpret_cast<const __half2*>(&v[t].y));
                acc.x += a0.x; acc.y += a0.y; acc.z += a1.x; acc.w += a1.y;
            }
        }
        for (; j < rem; j++) {
            int sj = __shfl_sync(0xffffffffu, s, j);
            uint2 hv = h2[(size_t)sj * 32 + lane];
            float2 a0 = __half22float2(*reinterpret_cast<const __half2*>(&hv.x));
            float2 a1 = __half22float2(*reinterpret_cast<const __half2*>(&hv.y));
            acc.x += a0.x; acc.y += a0.y; acc.z += a1.x; acc.w += a1.y;
        }
    }

    float4 bb = ((const float4*)b)[lane];
    float4 o;
    o.x = fmaxf(fmaf(di, acc.x, bb.x), 0.f);
    o.y = fmaxf(fmaf(di, acc.y, bb.y), 0.f);
    o.z = fmaxf(fmaf(di, acc.z, bb.z), 0.f);
    o.w = fmaxf(fmaf(di, acc.w, bb.w), 0.f);
    ((float4*)out)[(size_t)node * 32 + lane] = o;
}

// ---------------------------------------------------------------------------
extern "C" void kernel_launch(void* const* d_in, const int* in_sizes, int n_in,
                              void* d_out, int out_size) {
    const float* x   = (const float*)d_in[0];
    const void*  ei  = d_in[1];            // [2, E] int32 or int64 (probed)
    const float* W   = (const float*)d_in[2];
    const float* b   = (const float*)d_in[3];
    float*       out = (float*)d_out;

    const int n = in_sizes[0] / FDIM;      // 100000
    const int e = in_sizes[1] / 2;         // 3200000

    static cudaStream_t s1 = nullptr;
    static cudaEvent_t  ev_fork = nullptr, ev_res = nullptr, ev_scale = nullptr;
    if (s1 == nullptr) {
        cudaStreamCreateWithFlags(&s1, cudaStreamNonBlocking);
        cudaEventCreateWithFlags(&ev_fork,  cudaEventDisableTiming);
        cudaEventCreateWithFlags(&ev_res,   cudaEventDisableTiming);
        cudaEventCreateWithFlags(&ev_scale, cudaEventDisableTiming);
        cudaFuncSetAttribute(k_gemm_tf32, cudaFuncAttributeMaxDynamicSharedMemorySize,
                             64 * 1024);
    }

    // Fork at t=0: GEMM chain (no CSR dependencies) on s1
    cudaEventRecord(ev_fork, 0);
    cudaStreamWaitEvent(s1, ev_fork, 0);
    k_wprep<<<32, 256, 0, s1>>>(W);
    k_gemm_tf32<<<(n + 127) / 128, 256, 64 * 1024, s1>>>(x, n);

    // CSR chain on capture stream (g_deg/g_cursor self-restored each replay)
    k_probe<<<1, 1>>>(ei, n);
    int edge_threads = (e + 3) / 4;
    k_deg<<<(edge_threads + 255) / 256, 256>>>(ei, e, n);
    k_reserve<<<(n + 255) / 256, 256>>>(n);
    cudaEventRecord(ev_res, 0);

    // scale (in-place dis multiply) needs gemm (in-stream) + dis (event)
    cudaStreamWaitEvent(s1, ev_res, 0);
    int st = n * 16;
    k_scale<<<(st + 255) / 256, 256, 0, s1>>>(n);
    cudaEventRecord(ev_scale, s1);

    // fill (atomic-free) runs concurrent with gemm/scale
    k_fill<<<(edge_threads + 255) / 256, 256>>>(ei, e, n);

    // join: gather needs CSR (in-stream) + g_h (event)
    cudaStreamWaitEvent(0, ev_scale, 0);
    long long threads_total = (long long)n * 32;
    k_gather<<<(int)((threads_total + 255) / 256), 256>>>(b, out, n);
}

// round 15
// speedup vs baseline: 2.0435x; 2.0435x over previous
#include <cuda_runtime.h>
#include <cuda_fp16.h>
#include <cstdint>

#define MAXN 100000
#define MAXE 3200000
#define FDIM 128   // IN == OUT == 128

// Scratch (device globals: allocation-free per harness rules)
__device__ __half   g_h[(size_t)MAXN * FDIM];    // (x@W) fp16, then dis .* it (25.6 MB)
__device__ uint32_t g_Wfrag[16384];              // W tf32 fragment layout (64 KB)
__device__ float    g_dis[MAXN];                 // rsqrt(deg + 1)
__device__ int      g_deg[MAXN];                 // zero at steady state (reserve restores)
__device__ int      g_start[MAXN];
__device__ int      g_cur[MAXN];
__device__ int      g_csr[MAXE];                 // packed bins (12.8 MB)
__device__ int      g_cursor;                    // zero at steady state (gather restores)
__device__ int      g_is32;

// ---------------------------------------------------------------------------
// 0) dtype probe (idempotent; g_deg/g_cursor are self-restored by the pipeline)
__global__ void k_probe(const void* __restrict__ ei, int n) {
    const long long* p = (const long long*)ei;
    int is32 = 0;
    for (int k = 0; k < 64; k++) {
        long long v = p[k];
        if (v < 0 || v >= (long long)n) { is32 = 1; break; }
    }
    g_is32 = is32;
}

__device__ __forceinline__ int load_idx(const void* p, long long idx, int is32) {
    if (is32) return ((const int*)p)[idx];
    return (int)((const long long*)p)[idx];
}

// 1) histogram over dst — 4 edges per thread, int4 fast path (round-13 exact)
__global__ void k_deg(const void* __restrict__ ei, int e, int n) {
    int i = blockIdx.x * blockDim.x + threadIdx.x;
    int base = i * 4;
    if (base >= e) return;
    int is32 = g_is32;
    if (is32 && ((e & 3) == 0) && base + 4 <= e) {
        int4 d4 = ((const int4*)((const int*)ei + e))[i];
        if ((unsigned)d4.x < (unsigned)n) atomicAdd(&g_deg[d4.x], 1);
        if ((unsigned)d4.y < (unsigned)n) atomicAdd(&g_deg[d4.y], 1);
        if ((unsigned)d4.z < (unsigned)n) atomicAdd(&g_deg[d4.z], 1);
        if ((unsigned)d4.w < (unsigned)n) atomicAdd(&g_deg[d4.w], 1);
    } else {
        int hi = base + 4 < e ? base + 4 : e;
        for (int k = base; k < hi; k++) {
            int d = load_idx(ei, (long long)e + k, is32);
            if ((unsigned)d < (unsigned)n) atomicAdd(&g_deg[d], 1);
        }
    }
}

// 2) reserve bins + dis = rsqrt(deg+1); zero g_deg for the next replay
__global__ void k_reserve(int n) {
    int i = blockIdx.x * blockDim.x + threadIdx.x;
    if (i < n) {
        int d = g_deg[i];
        g_deg[i] = 0;                      // self-restore
        int st = atomicAdd(&g_cursor, d);
        g_start[i] = st;
        g_cur[i]   = st;
        g_dis[i]   = rsqrtf((float)(d + 1));
    }
}

// 3) fill CSR — 4 edges per thread, int4 fast path (round-13 exact, atomic)
__global__ void k_fill(const void* __restrict__ ei, int e, int n) {
    int i = blockIdx.x * blockDim.x + threadIdx.x;
    int base = i * 4;
    if (base >= e) return;
    int is32 = g_is32;
    if (is32 && ((e & 3) == 0) && base + 4 <= e) {
        int4 s4 = ((const int4*)((const int*)ei))[i];
        int4 d4 = ((const int4*)((const int*)ei + e))[i];
        if ((unsigned)d4.x < (unsigned)n && (unsigned)s4.x < (unsigned)n)
            g_csr[atomicAdd(&g_cur[d4.x], 1)] = s4.x;
        if ((unsigned)d4.y < (unsigned)n && (unsigned)s4.y < (unsigned)n)
            g_csr[atomicAdd(&g_cur[d4.y], 1)] = s4.y;
        if ((unsigned)d4.z < (unsigned)n && (unsigned)s4.z < (unsigned)n)
            g_csr[atomicAdd(&g_cur[d4.z], 1)] = s4.z;
        if ((unsigned)d4.w < (unsigned)n && (unsigned)s4.w < (unsigned)n)
            g_csr[atomicAdd(&g_cur[d4.w], 1)] = s4.w;
    } else {
        int hi = base + 4 < e ? base + 4 : e;
        for (int k = base; k < hi; k++) {
            int s = load_idx(ei, k, is32);
            int d = load_idx(ei, (long long)e + k, is32);
            if ((unsigned)d < (unsigned)n && (unsigned)s < (unsigned)n)
                g_csr[atomicAdd(&g_cur[d], 1)] = s;
        }
    }
}

// ---------------------------------------------------------------------------
// 4a) pre-swizzle W into tf32 m16n8k8 B-fragment layout (global, 64 KB)
__global__ void k_wprep(const float* __restrict__ W) {
    int i = blockIdx.x * blockDim.x + threadIdx.x;   // 8192 entries
    if (i >= 8192) return;
    int lane = i & 31;
    int nt   = (i >> 5) & 15;
    int ks   = i >> 9;
    int k    = ks * 8 + (lane & 3);
    int c    = nt * 8 + (lane >> 2);
    uint32_t t0, t1;
    asm("cvt.rna.tf32.f32 %0, %1;" : "=r"(t0) : "f"(W[(size_t)k * FDIM + c]));
    asm("cvt.rna.tf32.f32 %0, %1;" : "=r"(t1) : "f"(W[(size_t)(k + 4) * FDIM + c]));
    *(uint2*)&g_Wfrag[(size_t)i * 2] = make_uint2(t0, t1);
}

// 4b) GEMM: g_h = fp16(x @ W) raw; dis applied in place by k_scale.
__global__ void __launch_bounds__(256, 2)
k_gemm_tf32(const float* __restrict__ x, int n) {
    extern __shared__ uint32_t sm[];
    uint32_t* A = sm;            // [16 ks][8 w][32 lane][4 reg] = 64 KB

    const int row0 = blockIdx.x * 128;
    const int tid  = threadIdx.x;

    for (int i = tid; i < 16 * 8 * 32; i += 256) {
        int lane = i & 31;
        int w    = (i >> 5) & 7;
        int ks   = i >> 8;
        int r    = row0 + w * 16 + (lane >> 2);
        int c    = ks * 8 + (lane & 3);
        float v0 = 0.f, v1 = 0.f, v2 = 0.f, v3 = 0.f;
        if (r < n)     { v0 = x[(size_t)r * FDIM + c];       v2 = x[(size_t)r * FDIM + c + 4]; }
        if (r + 8 < n) { v1 = x[(size_t)(r + 8) * FDIM + c]; v3 = x[(size_t)(r + 8) * FDIM + c + 4]; }
        uint32_t t0, t1, t2, t3;
        asm("cvt.rna.tf32.f32 %0, %1;" : "=r"(t0) : "f"(v0));
        asm("cvt.rna.tf32.f32 %0, %1;" : "=r"(t1) : "f"(v1));
        asm("cvt.rna.tf32.f32 %0, %1;" : "=r"(t2) : "f"(v2));
        asm("cvt.rna.tf32.f32 %0, %1;" : "=r"(t3) : "f"(v3));
        *(uint4*)&A[(size_t)i * 4] = make_uint4(t0, t1, t2, t3);
    }
    __syncthreads();

    const int lane = tid & 31;
    const int w    = tid >> 5;

    float acc[16][4];
#pragma unroll
    for (int nt = 0; nt < 16; nt++) { acc[nt][0] = acc[nt][1] = acc[nt][2] = acc[nt][3] = 0.f; }

    const uint2* __restrict__ Bf = (const uint2*)g_Wfrag;

#pragma unroll
    for (int ks = 0; ks < 16; ks++) {
        uint4 a = *(const uint4*)&A[(((ks * 8 + w) * 32 + lane)) * 4];
#pragma unroll
        for (int nt = 0; nt < 16; nt++) {
            uint2 b = __ldg(&Bf[(ks * 16 + nt) * 32 + lane]);
            asm volatile(
                "mma.sync.aligned.m16n8k8.row.col.f32.tf32.tf32.f32 "
                "{%0,%1,%2,%3}, {%4,%5,%6,%7}, {%8,%9}, {%0,%1,%2,%3};"
                : "+f"(acc[nt][0]), "+f"(acc[nt][1]), "+f"(acc[nt][2]), "+f"(acc[nt][3])
                : "r"(a.x), "r"(a.y), "r"(a.z), "r"(a.w), "r"(b.x), "r"(b.y));
        }
    }

    // epilogue: fp16 raw (c0,c1 adjacent cols -> one half2)
    int r0 = row0 + w * 16 + (lane >> 2);
    int cp = lane & 3;                       // half2 index within an 8-col group
    if (r0 < n) {
        __half2* p = (__half2*)(g_h + (size_t)r0 * FDIM) + cp;
#pragma unroll
        for (int nt = 0; nt < 16; nt++)
            p[nt * 4] = __floats2half2_rn(acc[nt][0], acc[nt][1]);
    }
    if (r0 + 8 < n) {
        __half2* p = (__half2*)(g_h + (size_t)(r0 + 8) * FDIM) + cp;
#pragma unroll
        for (int nt = 0; nt < 16; nt++)
            p[nt * 4] = __floats2half2_rn(acc[nt][2], acc[nt][3]);
    }
}

// 4c) scale in place: g_h *= dis[row]  (fp16 read/write, fp32 math)
__global__ void k_scale(int n) {
    int i = blockIdx.x * blockDim.x + threadIdx.x;   // n*16 threads, 8 halves each
    if (i >= n * 16) return;
    int node = i >> 4;
    float d = g_dis[node];
    uint4 raw = ((const uint4*)g_h)[i];
    uint32_t r[4] = {raw.x, raw.y, raw.z, raw.w};
#pragma unroll
    for (int t = 0; t < 4; t++) {
        float2 f = __half22float2(*reinterpret_cast<const __half2*>(&r[t]));
        __half2 h = __floats2half2_rn(d * f.x, d * f.y);
        r[t] = *reinterpret_cast<const uint32_t*>(&h);
    }
    ((uint4*)g_h)[i] = make_uint4(r[0], r[1], r[2], r[3]);
}

// ---------------------------------------------------------------------------
// 5) gather: one warp per node; 8 row-loads in flight per lane (round-13 exact).
__global__ void k_gather(const float* __restrict__ b, float* __restrict__ out, int n) {
    int node = (blockIdx.x * blockDim.x + threadIdx.x) >> 5;
    int lane = threadIdx.x & 31;
    if (node >= n) return;
    if (node == 0 && lane == 0) g_cursor = 0;   // self-restore

    const uint2* __restrict__ h2 = (const uint2*)g_h;

    float di  = g_dis[node];
    int   s0  = g_start[node];
    int   deg = g_cur[node] - s0;

    uint2 raw = h2[(size_t)node * 32 + lane];
    float2 f0 = __half22float2(*reinterpret_cast<const __half2*>(&raw.x));
    float2 f1 = __half22float2(*reinterpret_cast<const __half2*>(&raw.y));
    float4 acc = make_float4(f0.x, f0.y, f1.x, f1.y);

    int nfull = deg & ~31;

    // full chunks: 32 coalesced indices, 4 batches of 8 in-flight loads
    for (int base = 0; base < nfull; base += 32) {
        int s = g_csr[s0 + base + lane];
#pragma unroll
        for (int jj = 0; jj < 32; jj += 8) {
            int sj[8];
#pragma unroll
            for (int t = 0; t < 8; t++) sj[t] = __shfl_sync(0xffffffffu, s, jj + t);
            uint2 v[8];
#pragma unroll
            for (int t = 0; t < 8; t++) v[t] = h2[(size_t)sj[t] * 32 + lane];
#pragma unroll
            for (int t = 0; t < 8; t++) {
                float2 a0 = __half22float2(*reinterpret_cast<const __half2*>(&v[t].x));
                float2 a1 = __half22float2(*reinterpret_cast<const __half2*>(&v[t].y));
                acc.x += a0.x; acc.y += a0.y; acc.z += a1.x; acc.w += a1.y;
            }
        }
    }

    // tail: 8-wide batches, then scalar
    int rem = deg - nfull;
    if (rem > 0) {
        int s = (lane < rem) ? g_csr[s0 + nfull + lane] : 0;
        int j = 0;
        for (; j + 8 <= rem; j += 8) {
            int sj[8];
#pragma unroll
            for (int t = 0; t < 8; t++) sj[t] = __shfl_sync(0xffffffffu, s, j + t);
            uint2 v[8];
#pragma unroll
            for (int t = 0; t < 8; t++) v[t] = h2[(size_t)sj[t] * 32 + lane];
#pragma unroll
            for (int t = 0; t < 8; t++) {
                float2 a0 = __half22float2(*reinterpret_cast<const __half2*>(&v[t].x));
                float2 a1 = __half22float2(*reinterpret_cast<const __half2*>(&v[t].y));
                acc.x += a0.x; acc.y += a0.y; acc.z += a1.x; acc.w += a1.y;
            }
        }
        for (; j < rem; j++) {
            int sj = __shfl_sync(0xffffffffu, s, j);
            uint2 hv = h2[(size_t)sj * 32 + lane];
            float2 a0 = __half22float2(*reinterpret_cast<const __half2*>(&hv.x));
            float2 a1 = __half22float2(*reinterpret_cast<const __half2*>(&hv.y));
            acc.x += a0.x; acc.y += a0.y; acc.z += a1.x; acc.w += a1.y;
        }
    }

    float4 bb = ((const float4*)b)[lane];
    float4 o;
    o.x = fmaxf(fmaf(di, acc.x, bb.x), 0.f);
    o.y = fmaxf(fmaf(di, acc.y, bb.y), 0.f);
    o.z = fmaxf(fmaf(di, acc.z, bb.z), 0.f);
    o.w = fmaxf(fmaf(di, acc.w, bb.w), 0.f);
    ((float4*)out)[(size_t)node * 32 + lane] = o;
}

// ---------------------------------------------------------------------------
extern "C" void kernel_launch(void* const* d_in, const int* in_sizes, int n_in,
                              void* d_out, int out_size) {
    const float* x   = (const float*)d_in[0];
    const void*  ei  = d_in[1];            // [2, E] int32 or int64 (probed)
    const float* W   = (const float*)d_in[2];
    const float* b   = (const float*)d_in[3];
    float*       out = (float*)d_out;

    const int n = in_sizes[0] / FDIM;      // 100000
    const int e = in_sizes[1] / 2;         // 3200000

    static cudaStream_t s1 = nullptr;
    static cudaEvent_t  ev_fork = nullptr, ev_res = nullptr, ev_scale = nullptr;
    if (s1 == nullptr) {
        cudaStreamCreateWithFlags(&s1, cudaStreamNonBlocking);
        cudaEventCreateWithFlags(&ev_fork,  cudaEventDisableTiming);
        cudaEventCreateWithFlags(&ev_res,   cudaEventDisableTiming);
        cudaEventCreateWithFlags(&ev_scale, cudaEventDisableTiming);
        cudaFuncSetAttribute(k_gemm_tf32, cudaFuncAttributeMaxDynamicSharedMemorySize,
                             64 * 1024);
    }

    // Fork at t=0: GEMM chain (no CSR dependencies) on s1
    cudaEventRecord(ev_fork, 0);
    cudaStreamWaitEvent(s1, ev_fork, 0);
    k_wprep<<<32, 256, 0, s1>>>(W);
    k_gemm_tf32<<<(n + 127) / 128, 256, 64 * 1024, s1>>>(x, n);

    // CSR chain on capture stream (g_deg/g_cursor self-restored each replay)
    k_probe<<<1, 1>>>(ei, n);
    int edge_threads = (e + 3) / 4;
    k_deg<<<(edge_threads + 255) / 256, 256>>>(ei, e, n);
    k_reserve<<<(n + 255) / 256, 256>>>(n);
    cudaEventRecord(ev_res, 0);

    // scale (in-place dis multiply) needs gemm (in-stream) + dis (event)
    cudaStreamWaitEvent(s1, ev_res, 0);
    int st = n * 16;
    k_scale<<<(st + 255) / 256, 256, 0, s1>>>(n);
    cudaEventRecord(ev_scale, s1);

    // fill runs concurrent with gemm/scale
    k_fill<<<(edge_threads + 255) / 256, 256>>>(ei, e, n);

    // join: gather needs CSR (in-stream) + g_h (event)
    cudaStreamWaitEvent(0, ev_scale, 0);
    long long threads_total = (long long)n * 32;
    k_gather<<<(int)((threads_total + 255) / 256), 256>>>(b, out, n);
}